// round 3
// baseline (speedup 1.0000x reference)
#include <cuda_runtime.h>
#include <cstdint>

#define NNODES 768
#define NFACES 256
#define NTOT   1024
#define E0     6144
#define EF     1536
#define ETOT   9216
#define C      64
#define ROWCAP 192
#define COLCAP 64
#define NKT    16
#define HSTR   68   // Hs stride (floats): 16B-aligned, conflict-friendly
#define GSTR   64   // Gs stride
#define SMEM_L2_BYTES ((64*HSTR + 64*GSTR) * 4 + 32 * 64 * 8)

// ---------------- device scratch ----------------
__device__ float g_node_all[NTOT * C];
__device__ float g_conn[ETOT * C];
__device__ float g_adjn[NTOT * NTOT];
__device__ float g_dinv[NTOT];
__device__ float g_srow[NTOT];
__device__ int   g_row_cnt[NTOT];
__device__ int   g_row_col[NTOT * ROWCAP];
__device__ float g_row_val[NTOT * ROWCAP];
__device__ int   g_col_cnt[NTOT];
__device__ int   g_col_edge[NTOT * COLCAP];
__device__ int   g_edge_src[ETOT];
__device__ float g_delta[67108864];
__device__ unsigned char g_sidx[NTOT * NKT * 64];
__device__ int   g_scnt[NTOT * NKT];

__device__ __forceinline__ float f2lo(uint64_t v) { return __uint_as_float((unsigned)v); }
__device__ __forceinline__ float f2hi(uint64_t v) { return __uint_as_float((unsigned)(v >> 32)); }
__device__ __forceinline__ void fma2(uint64_t& d, uint64_t a, uint64_t b) {
    asm("fma.rn.f32x2 %0, %1, %2, %0;" : "+l"(d) : "l"(a), "l"(b));
}
__device__ __forceinline__ uint64_t splat2(float a) {
    uint64_t v; asm("mov.b64 %0, {%1, %1};" : "=l"(v) : "f"(a)); return v;
}

// ---------------- zero / init ----------------
__global__ void k_zero() {
    int idx = blockIdx.x * blockDim.x + threadIdx.x;
    int stride = gridDim.x * blockDim.x;
    for (int i = idx; i < NTOT * NTOT; i += stride) g_adjn[i] = 0.f;
    if (idx < NTOT) { g_col_cnt[idx] = 0; g_row_cnt[idx] = 0; }
}

// ---------------- embedding MLPs ----------------
__global__ __launch_bounds__(128) void k_embed(
    const float* __restrict__ X, int R, int Din,
    const float* __restrict__ W1, const float* __restrict__ b1,
    const float* __restrict__ W2, const float* __restrict__ b2, int dst)
{
    float* Y = (dst == 0) ? g_node_all : (dst == 1) ? g_conn : (g_node_all + NNODES * C);
    __shared__ float Xs[16 * 144];
    __shared__ float Hs[16 * C];
    int r0 = blockIdx.x * 16;
    int t = threadIdx.x;
    for (int idx = t; idx < 16 * Din; idx += 128) {
        int r = idx / Din, d = idx % Din;
        Xs[r * Din + d] = (r0 + r < R) ? X[(size_t)(r0 + r) * Din + d] : 0.f;
    }
    __syncthreads();
    int lr = t >> 3;
    int c0 = (t & 7) * 8;
    float h[8];
#pragma unroll
    for (int q = 0; q < 8; q++) h[q] = b1[c0 + q];
    for (int d = 0; d < Din; d++) {
        float x = Xs[lr * Din + d];
        const float* w = W1 + d * C + c0;
#pragma unroll
        for (int q = 0; q < 8; q++) h[q] += x * w[q];
    }
#pragma unroll
    for (int q = 0; q < 8; q++) Hs[lr * C + c0 + q] = fmaxf(h[q], 0.f);
    __syncthreads();
    float y[8];
#pragma unroll
    for (int q = 0; q < 8; q++) y[q] = b2[c0 + q];
    for (int m = 0; m < C; m++) {
        float hm = Hs[lr * C + m];
        const float* w = W2 + m * C + c0;
#pragma unroll
        for (int q = 0; q < 8; q++) y[q] += hm * w[q];
    }
    if (r0 + lr < R) {
        float* yo = Y + (size_t)(r0 + lr) * C + c0;
#pragma unroll
        for (int q = 0; q < 8; q++) yo[q] = fmaxf(y[q], 0.f);
    }
}

// ---------------- conn rows for face edges ----------------
__global__ void k_conn_face() {
    int idx = blockIdx.x * blockDim.x + threadIdx.x;
    if (idx >= 2 * EF * C) return;
    int e = E0 + idx / C;
    int m = idx % C;
    int f;
    if (e < E0 + EF) f = (e - E0) / 6;
    else { int r = e - (E0 + EF); f = (1535 - r) / 6; }
    g_conn[e * C + m] = g_node_all[(NNODES + f) * C + m];
}

// ---------------- edges ----------------
__global__ void k_edges(const int* __restrict__ ei, const int* __restrict__ fn) {
    int e = blockIdx.x * blockDim.x + threadIdx.x;
    if (e >= ETOT) return;
    int s, d;
    if (e < E0)            { s = ei[e]; d = ei[E0 + e]; }
    else if (e < E0 + EF)  { int q = e - E0; s = fn[q]; d = NNODES + q / 6; }
    else                   { int r = e - (E0 + EF); int rr = 1535 - r; s = NNODES + rr / 6; d = fn[rr]; }
    g_edge_src[e] = s;
    atomicAdd(&g_adjn[s * NTOT + d], 1.0f);
    int p = atomicAdd(&g_col_cnt[d], 1);
    if (p < COLCAP) g_col_edge[d * COLCAP + p] = e;
}

__global__ void k_diag() {
    int i = blockIdx.x * blockDim.x + threadIdx.x;
    if (i < NTOT) g_adjn[i * NTOT + i] += 1.f;
}

// ---------------- degree ----------------
__global__ __launch_bounds__(256) void k_deg() {
    int i = blockIdx.x;
    float s = 0.f;
    for (int j = threadIdx.x; j < NTOT; j += 256) s += g_adjn[i * NTOT + j];
    __shared__ float red[8];
#pragma unroll
    for (int o = 16; o > 0; o >>= 1) s += __shfl_down_sync(0xffffffffu, s, o);
    if ((threadIdx.x & 31) == 0) red[threadIdx.x >> 5] = s;
    __syncthreads();
    if (threadIdx.x == 0) {
        float tot = 0.f;
        for (int w = 0; w < 8; w++) tot += red[w];
        g_dinv[i] = (tot > 0.f) ? (1.f / sqrtf(tot)) : 0.f;
    }
}

// ---------------- scale + CSR + row sums ----------------
__global__ __launch_bounds__(256) void k_scale_csr() {
    int i = blockIdx.x;
    __shared__ int cnt;
    __shared__ float red[8];
    if (threadIdx.x == 0) cnt = 0;
    __syncthreads();
    float di = g_dinv[i];
    float sv = 0.f;
    for (int j = threadIdx.x; j < NTOT; j += 256) {
        float v = g_adjn[i * NTOT + j];
        if (v != 0.f) {
            v *= di * g_dinv[j];
            g_adjn[i * NTOT + j] = v;
            sv += v;
            int p = atomicAdd(&cnt, 1);
            if (p < ROWCAP) { g_row_col[i * ROWCAP + p] = j; g_row_val[i * ROWCAP + p] = v; }
        }
    }
#pragma unroll
    for (int o = 16; o > 0; o >>= 1) sv += __shfl_down_sync(0xffffffffu, sv, o);
    if ((threadIdx.x & 31) == 0) red[threadIdx.x >> 5] = sv;
    __syncthreads();
    if (threadIdx.x == 0) {
        float tot = 0.f;
        for (int w = 0; w < 8; w++) tot += red[w];
        g_srow[i] = tot;
        g_row_cnt[i] = min(cnt, ROWCAP);
    }
}

// ---------------- layer 1: delta rows only ----------------
__global__ __launch_bounds__(256) void k_layer1(
    const float* __restrict__ plW, const float* __restrict__ plb)
{
    const int kt = blockIdx.x;
    const int j  = blockIdx.y;
    const int t  = threadIdx.x;
    __shared__ float Hs[64 * 65];
    __shared__ int nf;
    __shared__ int flist[64];
    if (t == 0) nf = 0;
    __syncthreads();

    const int kl = t & 63;
    const int m0 = (t >> 6) * 16;
    const int k  = kt * 64 + kl;

    float acc[16];
    bool fl = false;
    float ajk = g_adjn[j * NTOT + k];
    if (ajk != 0.f) {
        fl = true;
        const float* na = g_node_all + k * C + m0;
#pragma unroll
        for (int q = 0; q < 16; q++) acc[q] = ajk * na[q];
    } else {
#pragma unroll
        for (int q = 0; q < 16; q++) acc[q] = 0.f;
    }
    int cc = g_col_cnt[k]; if (cc > COLCAP) cc = COLCAP;
    for (int c = 0; c < cc; c++) {
        int e = g_col_edge[k * COLCAP + c];
        float a = g_adjn[j * NTOT + g_edge_src[e]];
        if (a != 0.f) {
            fl = true;
            const float4* cp = (const float4*)(g_conn + e * C + m0);
#pragma unroll
            for (int q = 0; q < 4; q++) {
                float4 v = cp[q];
                acc[4*q+0] += a * v.x; acc[4*q+1] += a * v.y;
                acc[4*q+2] += a * v.z; acc[4*q+3] += a * v.w;
            }
        }
    }
#pragma unroll
    for (int q = 0; q < 16; q++) Hs[kl * 65 + m0 + q] = acc[q];
    if ((t >> 6) == 0 && fl) { int p = atomicAdd(&nf, 1); flist[p] = kl; }
    __syncthreads();

    const int seg = j * NKT + kt;
    const int n = nf;
    const int c = t & 63;
    const float crc = fmaxf(plb[c], 0.f);
    const size_t segbase = (size_t)seg * 64 * 64;
    for (int idx = t >> 6; idx < n; idx += 4) {
        int row = flist[idx];
        float y = plb[c];
        const float* Hrow = Hs + row * 65;
#pragma unroll 16
        for (int m = 0; m < 64; m++) y += Hrow[m] * plW[m * 64 + c];
        g_delta[segbase + (size_t)idx * 64 + c] = fmaxf(y, 0.f) - crc;
        if (c == 0) g_sidx[seg * 64 + idx] = (unsigned char)row;
    }
    if (t == 0) g_scnt[seg] = n;
}

// ---------------- packed-f32x2 64xNC GEMM phase ----------------
// 256 threads = 2 K-groups x 128.  Per thread: 8 rows x CPT cols.
// As: shared input [64][asStride]; Wp: shared packed pairs [32][NC];
// Ps: shared output/partial [64][psStride] (group0 partial, group1 final).
template<int CPT, bool TOGLOBAL>
__device__ __forceinline__ void gemm_phase(
    const float* As, int asStride,
    const float2* Wp, const float* __restrict__ bias,
    float* Ps, int psStride, float* outG, int t, bool doRelu)
{
    constexpr int NC = CPT * 16;
    const int g  = t >> 7;
    const int tl = t & 127;
    const int r0 = (tl >> 4) << 3;
    const int c0 = (tl & 15) * CPT;
    uint64_t acc[8][CPT];
#pragma unroll
    for (int r = 0; r < 8; r++)
#pragma unroll
        for (int c = 0; c < CPT; c++) acc[r][c] = 0ull;
    const int mpBeg = g * 16;
#pragma unroll 4
    for (int mp = 0; mp < 16; mp++) {
        const int mm = mpBeg + mp;
        uint64_t a2[8];
#pragma unroll
        for (int r = 0; r < 8; r++)
            a2[r] = *(const uint64_t*)(As + (r0 + r) * asStride + 2 * mm);
        uint64_t b2[CPT];
        const uint64_t* wrow = (const uint64_t*)(Wp + mm * NC + c0);
#pragma unroll
        for (int c = 0; c < CPT; c++) b2[c] = wrow[c];
#pragma unroll
        for (int r = 0; r < 8; r++)
#pragma unroll
            for (int c = 0; c < CPT; c++) fma2(acc[r][c], a2[r], b2[c]);
    }
    if (g == 0) {
#pragma unroll
        for (int r = 0; r < 8; r++)
#pragma unroll
            for (int c = 0; c < CPT; c++)
                Ps[(r0 + r) * psStride + c0 + c] = f2lo(acc[r][c]) + f2hi(acc[r][c]);
    }
    __syncthreads();
    if (g == 1) {
#pragma unroll
        for (int r = 0; r < 8; r++) {
            float vals[CPT];
#pragma unroll
            for (int c = 0; c < CPT; c++) {
                float v = Ps[(r0 + r) * psStride + c0 + c]
                        + f2lo(acc[r][c]) + f2hi(acc[r][c]) + bias[c0 + c];
                vals[c] = doRelu ? fmaxf(v, 0.f) : v;
            }
            if (TOGLOBAL) {
#pragma unroll
                for (int c = 0; c < CPT; c += 2)
                    *(float2*)(outG + (size_t)(r0 + r) * NC + c0 + c) = make_float2(vals[c], vals[c + 1]);
            } else {
#pragma unroll
                for (int c = 0; c < CPT; c++)
                    Ps[(r0 + r) * psStride + c0 + c] = vals[c];
            }
        }
    }
    __syncthreads();
}

__device__ __forceinline__ void packW(float2* Wp, const float* __restrict__ W, int NC, int t) {
    for (int idx = t; idx < 32 * NC; idx += 256) {
        int mp = idx / NC, c = idx % NC;
        Wp[idx] = make_float2(W[(2 * mp) * NC + c], W[(2 * mp + 1) * NC + c]);
    }
}

// ---------------- layer 2 fused ----------------
__global__ __launch_bounds__(256) void k_layer2(
    const float* __restrict__ plb0,
    const float* __restrict__ plW, const float* __restrict__ plb,
    const float* __restrict__ oW1, const float* __restrict__ ob1,
    const float* __restrict__ oW2, const float* __restrict__ ob2,
    float* __restrict__ out)
{
    extern __shared__ float smem[];
    float*  Hs = smem;                       // [64][HSTR]
    float*  Gs = smem + 64 * HSTR;           // [64][GSTR]
    float2* Wp = (float2*)(smem + 64 * HSTR + 64 * GSTR);  // [32][64]

    const int i  = blockIdx.x;
    const int kt = blockIdx.y;
    const int t  = threadIdx.x;

    // Phase A: Hs[k,:] = s_i*cr + sum_j a_ij * delta(j,k,:)
    {
        const int kl = t & 63;
        const int m0 = (t >> 6) * 16;
        const float sI = g_srow[i];
#pragma unroll
        for (int q = 0; q < 16; q++)
            Hs[kl * HSTR + m0 + q] = sI * fmaxf(plb0[m0 + q], 0.f);
        __syncthreads();

        const int rn = g_row_cnt[i];
        const int*   rc = g_row_col + i * ROWCAP;
        const float* rv = g_row_val + i * ROWCAP;
        const int p   = t >> 2;
        const int sub = (t & 3) * 16;
        for (int r = 0; r < rn; r++) {
            int j = rc[r];
            float a = rv[r];
            int seg = j * NKT + kt;
            int cnt = g_scnt[seg];
            if (p < cnt) {
                int klq = g_sidx[seg * 64 + p];
                const uint64_t* dp = (const uint64_t*)(g_delta + ((size_t)seg * 64 + p) * 64 + sub);
                uint64_t* h = (uint64_t*)(Hs + klq * HSTR + sub);
                uint64_t aa = splat2(a);
#pragma unroll
                for (int q = 0; q < 8; q++) {
                    uint64_t hv = h[q];
                    fma2(hv, aa, dp[q]);
                    h[q] = hv;
                }
            }
            __syncthreads();
        }
    }

    // Phase B: Gs = relu(Hs @ plW1 + plb1)
    packW(Wp, plW, 64, t);
    __syncthreads();
    gemm_phase<4, false>(Hs, HSTR, Wp, plb, Gs, GSTR, nullptr, t, true);

    // Phase C: Hs = relu(Gs @ oW1 + ob1)
    packW(Wp, oW1, 64, t);
    __syncthreads();
    gemm_phase<4, false>(Gs, GSTR, Wp, ob1, Hs, HSTR, nullptr, t, true);

    // Phase D: out = Hs @ oW2 + ob2
    packW(Wp, oW2, 32, t);
    __syncthreads();
    float* outG = out + ((size_t)i * NTOT + (size_t)kt * 64) * 32;
    gemm_phase<2, true>(Hs, HSTR, Wp, ob2, Gs, GSTR, outG, t, false);
}

// ---------------- launch ----------------
extern "C" void kernel_launch(void* const* d_in, const int* in_sizes, int n_in,
                              void* d_out, int out_size)
{
    const float* node_x = (const float*)d_in[0];
    const float* edge_x = (const float*)d_in[1];
    const float* face_x = (const float*)d_in[2];
    const float* nW1 = (const float*)d_in[3];  const float* nb1 = (const float*)d_in[4];
    const float* nW2 = (const float*)d_in[5];  const float* nb2 = (const float*)d_in[6];
    const float* eW1 = (const float*)d_in[7];  const float* eb1 = (const float*)d_in[8];
    const float* eW2 = (const float*)d_in[9];  const float* eb2 = (const float*)d_in[10];
    const float* fW1 = (const float*)d_in[11]; const float* fb1 = (const float*)d_in[12];
    const float* fW2 = (const float*)d_in[13]; const float* fb2 = (const float*)d_in[14];
    const float* oW1 = (const float*)d_in[15]; const float* ob1 = (const float*)d_in[16];
    const float* oW2 = (const float*)d_in[17]; const float* ob2 = (const float*)d_in[18];
    const float* plW = (const float*)d_in[19]; const float* plb = (const float*)d_in[20];
    const int* edge_index = (const int*)d_in[21];
    const int* face_nodes = (const int*)d_in[22];
    float* out = (float*)d_out;

    cudaFuncSetAttribute(k_layer2, cudaFuncAttributeMaxDynamicSharedMemorySize, SMEM_L2_BYTES);

    k_zero<<<512, 256>>>();
    k_embed<<<NNODES / 16, 128>>>(node_x, NNODES, 144, nW1, nb1, nW2, nb2, 0);
    k_embed<<<E0 / 16, 128>>>(edge_x, E0, 144, eW1, eb1, eW2, eb2, 1);
    k_embed<<<NFACES / 16, 128>>>(face_x, NFACES, 12, fW1, fb1, fW2, fb2, 2);
    k_conn_face<<<(2 * EF * C + 255) / 256, 256>>>();
    k_edges<<<(ETOT + 255) / 256, 256>>>(edge_index, face_nodes);
    k_diag<<<(NTOT + 255) / 256, 256>>>();
    k_deg<<<NTOT, 256>>>();
    k_scale_csr<<<NTOT, 256>>>();
    k_layer1<<<dim3(NKT, NTOT), 256>>>(plW, plb);
    k_layer2<<<dim3(NTOT, NKT), 256, SMEM_L2_BYTES>>>(plb,
                                       plW + 4096, plb + 64,
                                       oW1, ob1, oW2, ob2, out);
    (void)in_sizes; (void)n_in; (void)out_size;
}